// round 15
// baseline (speedup 1.0000x reference)
#include <cuda_runtime.h>
#include <cuda_bf16.h>
#include <cstdint>

// BatchDepthwiseCrossCorrelation via warp TF32 MMA (m16n8k8, RNA), half-plane CTAs,
// dual-tile mainloop, const-immediate stores, division-free prologue.
//   x: [8,256,64,64] f32; templates: [8,8,256,7,7] f32; out: [8,8,256,64,64] f32
// Per channel c: out[p, nt] = sum_tap patch[p, tap] * t[nt, tap]
// MMA tile: rows 0-7 = (y, x0+r), rows 8-15 = (y+1, x0+r); cols = nt; 7 MMAs (ky 0..6).

#define BSNC   2048
#define HI     64
#define WI     64
#define PLANE  (HI*WI)
#define PAD    3
#define NT     8
#define HROWS  32
#define SROWS  38
#define SPW    72
#define NTHREADS 256

__device__ __forceinline__ void mma_tf32(float& d0, float& d1, float& d2, float& d3,
                                         uint32_t a0, uint32_t a1, uint32_t a2, uint32_t a3,
                                         uint32_t b0, uint32_t b1) {
    asm volatile(
        "mma.sync.aligned.m16n8k8.row.col.f32.tf32.tf32.f32 "
        "{%0,%1,%2,%3}, {%4,%5,%6,%7}, {%8,%9}, {%0,%1,%2,%3};"
        : "+f"(d0), "+f"(d1), "+f"(d2), "+f"(d3)
        : "r"(a0), "r"(a1), "r"(a2), "r"(a3), "r"(b0), "r"(b1));
}

__device__ __forceinline__ uint32_t tf32_rna(float v) {
    uint32_t r;
    asm("cvt.rna.tf32.f32 %0, %1;" : "=r"(r) : "f"(v));
    return r;
}

__global__ __launch_bounds__(NTHREADS, 4)
void dwxcorr_tf32_kernel(const float* __restrict__ x,
                         const float* __restrict__ tm,
                         float* __restrict__ out)
{
    __shared__ uint2 s_pair[SROWS][SPW];                // {tf32 x(cc-3), tf32 x(cc+1)}
    __shared__ __align__(16) uint32_t s_tmpl[NT][64];   // tf32 templates, tap = ky*8+kx

    const int c   = blockIdx.x >> 1;            // fused (b, ch) channel
    const int y0  = (blockIdx.x & 1) * HROWS;   // top output row of this half
    const int tid = threadIdx.x;
    const int wid = tid >> 5;
    const int lane = tid & 31;
    const int q = lane & 3;                     // k index (A cols q, q+4); nt pair 2q
    const int r = lane >> 4 == 0 ? (lane >> 2) : (lane >> 2); // r = lane>>2 (kept explicit)

    // ---- Prologue: division-free padded pair-plane fill ----
    {
        const float* xc = x + (size_t)c * PLANE;
        const int tr = tid >> 3;        // 0..31 (row group)
        const int tc = tid & 7;         // 0..7  (column lane)
        #pragma unroll
        for (int pass = 0; pass < 2; pass++) {
            int rr = tr + pass * 32;
            if (rr < SROWS) {
                int gy = y0 + rr - PAD;
                bool yok = (gy >= 0) && (gy < HI);
                const float* row = xc + (size_t)gy * WI;
                #pragma unroll
                for (int j = 0; j < 9; j++) {
                    int cc = tc + j * 8;                // 0..71
                    int gx0 = cc - PAD;                 // pair elem 0
                    int gx1 = cc + 1;                   // pair elem 1 (x+4 tap)
                    uint32_t v0 = (yok && gx0 >= 0 && gx0 < WI) ? tf32_rna(row[gx0]) : 0u;
                    uint32_t v1 = (yok && gx1 < WI) ? tf32_rna(row[gx1]) : 0u;
                    s_pair[rr][cc] = make_uint2(v0, v1);
                }
            }
        }
    }
    // Templates: zero then scatter taps into [nt][ky*8+kx] (kx=7, ky=7 stay zero).
    for (int i = tid; i < NT * 64; i += NTHREADS) ((uint32_t*)s_tmpl)[i] = 0u;
    __syncthreads();
    for (int i = tid; i < NT * 49; i += NTHREADS) {
        int nt = i / 49, tap = i - nt * 49;
        int ky = tap / 7, kx = tap - ky * 7;
        s_tmpl[nt][ky * 8 + kx] = tf32_rna(tm[((size_t)nt * BSNC + c) * 49 + tap]);
    }
    __syncthreads();

    // ---- B fragments: tb0[ky] = t[nt=r][ky*8+q], tb1[ky] = +4 ----
    uint32_t tb0[7], tb1[7];
    #pragma unroll
    for (int ky = 0; ky < 7; ky++) {
        tb0[ky] = s_tmpl[r][ky * 8 + q];
        tb1[ky] = s_tmpl[r][ky * 8 + q + 4];
    }

    const size_t planeN = (size_t)BSNC * PLANE;

    // ---- Mainloop: one 8-wide x-strip per warp, 8 dual-tiles (4 y-rows each) ----
    const int x0 = wid << 3;
    const int xf = x0 + r + q;                  // fixed fragment x (pair covers xf, xf+4)
    float* P0 = out + (size_t)c * PLANE + (size_t)y0 * WI
              + (size_t)(x0 + r) + (size_t)(2 * q) * planeN;   // nt = 2q plane
    float* P1 = P0 + planeN;                                    // nt = 2q+1 plane

    uint2 W[SROWS];                             // constant-indexed window

    #pragma unroll
    for (int a = 0; a < 10; a++) W[a] = s_pair[a][xf];

    #pragma unroll
    for (int d = 0; d < 8; d++) {
        const int ty = 4 * d;
        // Two independent tiles: A = rows (ty, ty+1), B = rows (ty+2, ty+3).
        float A0 = 0.f, A1 = 0.f, A2 = 0.f, A3 = 0.f;
        float B0 = 0.f, B1 = 0.f, B2 = 0.f, B3 = 0.f;

        #pragma unroll
        for (int ky = 0; ky < 7; ky++) {
            mma_tf32(A0, A1, A2, A3,
                     W[ty + ky].x, W[ty + ky + 1].x, W[ty + ky].y, W[ty + ky + 1].y,
                     tb0[ky], tb1[ky]);
            mma_tf32(B0, B1, B2, B3,
                     W[ty + ky + 2].x, W[ty + ky + 3].x, W[ty + ky + 2].y, W[ty + ky + 3].y,
                     tb0[ky], tb1[ky]);
        }

        // Stores: compile-time float offsets (row stride WI=64), no address math.
        P0[(ty + 0) * WI] = A0;  P1[(ty + 0) * WI] = A1;
        P0[(ty + 1) * WI] = A2;  P1[(ty + 1) * WI] = A3;
        P0[(ty + 2) * WI] = B0;  P1[(ty + 2) * WI] = B1;
        P0[(ty + 3) * WI] = B2;  P1[(ty + 3) * WI] = B3;

        if (d < 7) {
            W[ty + 10] = s_pair[ty + 10][xf];
            W[ty + 11] = s_pair[ty + 11][xf];
            W[ty + 12] = s_pair[ty + 12][xf];
            W[ty + 13] = s_pair[ty + 13][xf];
        }
    }
}

extern "C" void kernel_launch(void* const* d_in, const int* in_sizes, int n_in,
                              void* d_out, int out_size)
{
    const float* x  = (const float*)d_in[0];
    const float* tm = (const float*)d_in[1];
    float* out      = (float*)d_out;
    dwxcorr_tf32_kernel<<<BSNC * 2, NTHREADS>>>(x, tm, out);
}

// round 16
// speedup vs baseline: 1.2539x; 1.2539x over previous
#include <cuda_runtime.h>
#include <cuda_bf16.h>
#include <cstdint>

// BatchDepthwiseCrossCorrelation via warp TF32 MMA (m16n8k8, RNA), quarter-plane CTAs,
// 48-register build for 10 CTAs/SM (occupancy experiment on the R12 base).
//   x: [8,256,64,64] f32; templates: [8,8,256,7,7] f32; out: [8,8,256,64,64] f32
// Per channel c: out[p, nt] = sum_tap patch[p, tap] * t[nt, tap]
// MMA tile: rows 0-7 = (ty, x0+r), rows 8-15 = (ty+1, x0+r); cols = nt; 7 MMAs (ky 0..6).

#define BSNC   2048
#define HI     64
#define WI     64
#define PLANE  (HI*WI)
#define PAD    3
#define NT     8
#define QROWS  16                 // output rows per CTA (quarter plane)
#define SROWS  23                 // padded plane rows staged
#define SPW    72                 // pair-plane row pitch (uint2)
#define NTHREADS 128

__device__ __forceinline__ void mma_tf32(float& d0, float& d1, float& d2, float& d3,
                                         uint32_t a0, uint32_t a1, uint32_t a2, uint32_t a3,
                                         uint32_t b0, uint32_t b1) {
    asm volatile(
        "mma.sync.aligned.m16n8k8.row.col.f32.tf32.tf32.f32 "
        "{%0,%1,%2,%3}, {%4,%5,%6,%7}, {%8,%9}, {%0,%1,%2,%3};"
        : "+f"(d0), "+f"(d1), "+f"(d2), "+f"(d3)
        : "r"(a0), "r"(a1), "r"(a2), "r"(a3), "r"(b0), "r"(b1));
}

__device__ __forceinline__ uint32_t tf32_rna(float v) {
    uint32_t r;
    asm("cvt.rna.tf32.f32 %0, %1;" : "=r"(r) : "f"(v));
    return r;
}

__global__ __launch_bounds__(NTHREADS, 10)
void dwxcorr_tf32_kernel(const float* __restrict__ x,
                         const float* __restrict__ tm,
                         float* __restrict__ out)
{
    __shared__ uint2 s_pair[SROWS][SPW];                // {tf32 x(cc-3), tf32 x(cc+1)}
    __shared__ __align__(16) uint32_t s_tmpl[NT][64];   // tf32 templates, tap = ky*8+kx

    const int c   = blockIdx.x >> 2;            // fused (b, ch) channel
    const int y0  = (blockIdx.x & 3) * QROWS;   // top output row of this quarter
    const int tid = threadIdx.x;
    const int wid = tid >> 5;
    const int lane = tid & 31;
    const int q = lane & 3;                     // k index (A cols q, q+4); nt pair 2q
    const int r = lane >> 2;                    // A row / B col (nt)

    // ---- Prologue: zero-fill + fill valid rows (R12-identical) ----
    for (int i = tid; i < SROWS * SPW; i += NTHREADS)
        ((uint2*)s_pair)[i] = make_uint2(0u, 0u);
    for (int i = tid; i < NT * 64; i += NTHREADS) ((uint32_t*)s_tmpl)[i] = 0u;
    __syncthreads();

    {
        const int a0 = (y0 == 0) ? PAD : 0;
        int a1 = 66 - y0; if (a1 > SROWS - 1) a1 = SROWS - 1;
        const int nrows = a1 - a0 + 1;
        const float* xc = x + (size_t)c * PLANE;
        for (int i = tid; i < nrows * 71; i += NTHREADS) {
            int rr = i / 71;
            int cc = i - rr * 71;
            int gy = y0 + (a0 + rr) - PAD;
            const float* row = xc + (size_t)gy * WI;
            int gx0 = cc - PAD;
            int gx1 = cc + 1;
            uint32_t v0 = (gx0 >= 0 && gx0 < WI) ? tf32_rna(row[gx0]) : 0u;
            uint32_t v1 = (gx1 < WI) ? tf32_rna(row[gx1]) : 0u;
            s_pair[a0 + rr][cc] = make_uint2(v0, v1);
        }
    }
    for (int i = tid; i < NT * 49; i += NTHREADS) {
        int nt = i / 49, tap = i - nt * 49;
        int ky = tap / 7, kx = tap - ky * 7;
        s_tmpl[nt][ky * 8 + kx] = tf32_rna(tm[((size_t)nt * BSNC + c) * 49 + tap]);
    }
    __syncthreads();

    // ---- B fragments: b0[ky] = t[nt=r][ky*8+q], b1[ky] = +4 ----
    uint32_t b0[7], b1[7];
    #pragma unroll
    for (int ky = 0; ky < 7; ky++) {
        b0[ky] = s_tmpl[r][ky * 8 + q];
        b1[ky] = s_tmpl[r][ky * 8 + q + 4];
    }

    const size_t planeN = (size_t)BSNC * PLANE;

    // ---- Mainloop: 2 x-strips per warp (serial), 8 y-pair tiles per strip ----
    #pragma unroll 1
    for (int sidx = 0; sidx < 2; sidx++) {
        const int x0 = (wid + 4 * sidx) * 8;
        const int xf = x0 + r + q;              // fixed fragment x (pair covers xf, xf+4)
        float* obase = out + (size_t)c * PLANE + (size_t)y0 * WI
                     + (size_t)(x0 + r) + (size_t)(2 * q) * planeN;

        uint2 W[SROWS];                         // constant-indexed, live range ~10 rows

        #pragma unroll
        for (int a = 0; a < 8; a++) W[a] = s_pair[a][xf];

        #pragma unroll
        for (int typ = 0; typ < 8; typ++) {
            const int ty = 2 * typ;
            float d0 = 0.f, d1 = 0.f, d2 = 0.f, d3 = 0.f;

            #pragma unroll
            for (int ky = 0; ky < 7; ky++) {
                mma_tf32(d0, d1, d2, d3,
                         W[ty + ky].x, W[ty + ky + 1].x,
                         W[ty + ky].y, W[ty + ky + 1].y,
                         b0[ky], b1[ky]);
            }

            float* ob = obase + (size_t)ty * WI;
            ob[0]           = d0;   // (pixel ty,   nt 2q)
            ob[planeN]      = d1;   // (pixel ty,   nt 2q+1)
            ob[WI]          = d2;   // (pixel ty+1, nt 2q)
            ob[planeN + WI] = d3;   // (pixel ty+1, nt 2q+1)

            if (typ < 7) {
                W[ty + 8] = s_pair[ty + 8][xf];
                W[ty + 9] = s_pair[ty + 9][xf];
            }
        }
    }
}

extern "C" void kernel_launch(void* const* d_in, const int* in_sizes, int n_in,
                              void* d_out, int out_size)
{
    const float* x  = (const float*)d_in[0];
    const float* tm = (const float*)d_in[1];
    float* out      = (float*)d_out;
    dwxcorr_tf32_kernel<<<BSNC * 4, NTHREADS>>>(x, tm, out);
}

// round 17
// speedup vs baseline: 1.5490x; 1.2353x over previous
#include <cuda_runtime.h>
#include <cuda_bf16.h>
#include <cstdint>

// BatchDepthwiseCrossCorrelation via warp TF32 MMA (m16n8k8, RNA), quarter-plane CTAs,
// 48-register build (10 CTAs/SM), fused division-free prologue.
//   x: [8,256,64,64] f32; templates: [8,8,256,7,7] f32; out: [8,8,256,64,64] f32
// Per channel c: out[p, nt] = sum_tap patch[p, tap] * t[nt, tap]
// MMA tile: rows 0-7 = (ty, x0+r), rows 8-15 = (ty+1, x0+r); cols = nt; 7 MMAs (ky 0..6).

#define BSNC   2048
#define HI     64
#define WI     64
#define PLANE  (HI*WI)
#define PAD    3
#define NT     8
#define QROWS  16                 // output rows per CTA (quarter plane)
#define SROWS  23                 // padded plane rows staged
#define SPW    72                 // pair-plane row pitch (uint2)
#define NTHREADS 128

__device__ __forceinline__ void mma_tf32(float& d0, float& d1, float& d2, float& d3,
                                         uint32_t a0, uint32_t a1, uint32_t a2, uint32_t a3,
                                         uint32_t b0, uint32_t b1) {
    asm volatile(
        "mma.sync.aligned.m16n8k8.row.col.f32.tf32.tf32.f32 "
        "{%0,%1,%2,%3}, {%4,%5,%6,%7}, {%8,%9}, {%0,%1,%2,%3};"
        : "+f"(d0), "+f"(d1), "+f"(d2), "+f"(d3)
        : "r"(a0), "r"(a1), "r"(a2), "r"(a3), "r"(b0), "r"(b1));
}

__device__ __forceinline__ uint32_t tf32_rna(float v) {
    uint32_t r;
    asm("cvt.rna.tf32.f32 %0, %1;" : "=r"(r) : "f"(v));
    return r;
}

__global__ __launch_bounds__(NTHREADS, 10)
void dwxcorr_tf32_kernel(const float* __restrict__ x,
                         const float* __restrict__ tm,
                         float* __restrict__ out)
{
    __shared__ uint2 s_pair[SROWS][SPW];                // {tf32 x(cc-3), tf32 x(cc+1)}
    __shared__ __align__(16) uint32_t s_tmpl[NT][64];   // tf32 templates, tap = ky*8+kx

    const int c   = blockIdx.x >> 2;            // fused (b, ch) channel
    const int y0  = (blockIdx.x & 3) * QROWS;   // top output row of this quarter
    const int tid = threadIdx.x;
    const int wid = tid >> 5;
    const int lane = tid & 31;
    const int q = lane & 3;                     // k index (A cols q, q+4); nt pair 2q
    const int r = lane >> 2;                    // A row / B col (nt)

    // ---- Fused prologue: single division-free pass, every cell written once ----
    {
        const float* xc = x + (size_t)c * PLANE;
        const int tr = tid >> 3;        // 0..15 (row group)
        const int tc = tid & 7;         // 0..7  (column lane)
        #pragma unroll
        for (int pass = 0; pass < 2; pass++) {
            const int rr = tr + pass * 16;
            if (rr < SROWS) {
                const int gy = y0 + rr - PAD;
                const bool yok = (gy >= 0) && (gy < HI);
                const float* row = xc + (size_t)gy * WI;
                #pragma unroll
                for (int j = 0; j < 9; j++) {
                    const int cc  = tc + j * 8;         // 0..71
                    const int gx0 = cc - PAD;           // pair elem 0
                    const int gx1 = cc + 1;             // pair elem 1 (x+4 tap)
                    uint32_t v0 = (yok && gx0 >= 0 && gx0 < WI) ? tf32_rna(row[gx0]) : 0u;
                    uint32_t v1 = (yok && gx1 < WI) ? tf32_rna(row[gx1]) : 0u;
                    s_pair[rr][cc] = make_uint2(v0, v1);
                }
            }
        }
    }
    // Templates: iterate padded 64-tap space directly (kx=7 / ky=7 cells get 0).
    {
        const float* tc_base = tm + (size_t)c * 49;
        #pragma unroll
        for (int j = 0; j < 4; j++) {
            const int i  = tid + j * NTHREADS;          // 0..511
            const int nt = i >> 6;
            const int t6 = i & 63;
            const int ky = t6 >> 3;
            const int kx = t6 & 7;
            float v = (kx < 7 && ky < 7)
                    ? tc_base[(size_t)nt * (BSNC * 49) + ky * 7 + kx] : 0.0f;
            s_tmpl[nt][t6] = tf32_rna(v);
        }
    }
    __syncthreads();

    // ---- B fragments: b0[ky] = t[nt=r][ky*8+q], b1[ky] = +4 ----
    uint32_t b0[7], b1[7];
    #pragma unroll
    for (int ky = 0; ky < 7; ky++) {
        b0[ky] = s_tmpl[r][ky * 8 + q];
        b1[ky] = s_tmpl[r][ky * 8 + q + 4];
    }

    const size_t planeN = (size_t)BSNC * PLANE;

    // ---- Mainloop: 2 x-strips per warp (serial), 8 y-pair tiles per strip ----
    #pragma unroll 1
    for (int sidx = 0; sidx < 2; sidx++) {
        const int x0 = (wid + 4 * sidx) * 8;
        const int xf = x0 + r + q;              // fixed fragment x (pair covers xf, xf+4)
        float* obase = out + (size_t)c * PLANE + (size_t)y0 * WI
                     + (size_t)(x0 + r) + (size_t)(2 * q) * planeN;

        uint2 W[SROWS];                         // constant-indexed, live range ~10 rows

        #pragma unroll
        for (int a = 0; a < 8; a++) W[a] = s_pair[a][xf];

        #pragma unroll
        for (int typ = 0; typ < 8; typ++) {
            const int ty = 2 * typ;
            float d0 = 0.f, d1 = 0.f, d2 = 0.f, d3 = 0.f;

            #pragma unroll
            for (int ky = 0; ky < 7; ky++) {
                mma_tf32(d0, d1, d2, d3,
                         W[ty + ky].x, W[ty + ky + 1].x,
                         W[ty + ky].y, W[ty + ky + 1].y,
                         b0[ky], b1[ky]);
            }

            float* ob = obase + (size_t)ty * WI;
            ob[0]           = d0;   // (pixel ty,   nt 2q)
            ob[planeN]      = d1;   // (pixel ty,   nt 2q+1)
            ob[WI]          = d2;   // (pixel ty+1, nt 2q)
            ob[planeN + WI] = d3;   // (pixel ty+1, nt 2q+1)

            if (typ < 7) {
                W[ty + 8] = s_pair[ty + 8][xf];
                W[ty + 9] = s_pair[ty + 9][xf];
            }
        }
    }
}

extern "C" void kernel_launch(void* const* d_in, const int* in_sizes, int n_in,
                              void* d_out, int out_size)
{
    const float* x  = (const float*)d_in[0];
    const float* tm = (const float*)d_in[1];
    float* out      = (float*)d_out;
    dwxcorr_tf32_kernel<<<BSNC * 4, NTHREADS>>>(x, tm, out);
}